// round 1
// baseline (speedup 1.0000x reference)
#include <cuda_runtime.h>
#include <cuda_bf16.h>

// DTW over a 2048x2048 cost grid, anti-diagonal wavefront on ONE SM.
// Thread t owns rows (2t, 2t+1). Per diagonal d it computes both cells:
//   row 2t   : up   = neighbor thread's row (2t-1) value at d-1  -> shfl_up(p1) / smem boundary
//              left = own row value at d-1                        -> p0
//              diag = neighbor row (2t-1) at d-2                  -> previous step's shuffled up
//   row 2t+1 : up   = own row 2t at d-1                           -> p0
//              left = own row 2t+1 at d-1                         -> p1
//              diag = own row 2t at d-2                           -> pp0
// Out-of-range cells hold +inf (or harmless finite garbage past the right
// edge, which provably never flows into valid cells), so no predicates.

#define NLEN 2048
#define NDIAG (2 * NLEN - 1)
#define FINF __int_as_float(0x7f800000)

__global__ __launch_bounds__(1024, 1)
void dtw_wavefront_kernel(const float* __restrict__ x,
                          const float* __restrict__ y,
                          float* __restrict__ out)
{
    __shared__ float ysp[3 * NLEN];   // y padded: ysp[NLEN + j] = y[j], 0 elsewhere
    __shared__ float bnd[2][32];      // per-warp bottom-row value, double buffered by diag parity

    const int t    = threadIdx.x;
    const int lane = t & 31;
    const int wid  = t >> 5;

    // Stage padded y into shared memory (pads are 0.0f; padded reads feed only
    // garbage cells that never reach valid cells).
    for (int k = t; k < 3 * NLEN; k += 1024) {
        float v = 0.0f;
        int j = k - NLEN;
        if ((unsigned)j < (unsigned)NLEN) v = y[j];
        ysp[k] = v;
    }
    if (t < 64) bnd[t >> 5][t & 31] = FINF;

    // x for this thread's two rows (coalesced float2 load).
    const float2 xv = reinterpret_cast<const float2*>(x)[t];
    const float x0 = xv.x;   // row i0 = 2t
    const float x1 = xv.y;   // row i1 = 2t+1

    // DP state registers (values at previous diagonals), init to "nothing yet".
    float p0    = FINF;                       // row i0 at d-1
    float p1    = FINF;                       // row i1 at d-1
    float pp0   = FINF;                       // row i0 at d-2
    float diag0 = (t == 0) ? 0.0f : FINF;     // virtual DTW[-1][-1] = 0 seeds cell (0,0)

    __syncthreads();

    // yb0[d] == y[d - i0] (padded), yb0[d-1] == y[d - i0 - 1] == y[j1]
    const float* yb0 = ysp + NLEN - 2 * t;

    #pragma unroll 2
    for (int d = 0; d < NDIAG; ++d) {
        // Cross-thread value: neighbor's row (2t-1) at diagonal d-1.
        float up0 = __shfl_up_sync(0xffffffffu, p1, 1);
        if (lane == 0) up0 = (wid == 0) ? FINF : bnd[d & 1][wid - 1];

        const float yv0 = yb0[d];
        const float yv1 = yb0[d - 1];
        const float dy0 = x0 - yv0;
        const float dy1 = x1 - yv1;

        const float n0 = fmaf(dy0, dy0, fminf(fminf(up0, diag0), p0));
        const float n1 = fmaf(dy1, dy1, fminf(fminf(p0, pp0), p1));

        // Publish this warp's bottom row (i = 64*wid + 63) for the next warp's
        // lane 0 to consume at step d+1 (double buffered => 1 barrier/step).
        if (lane == 31) bnd[(d + 1) & 1][wid] = n1;

        // Rotate state.
        diag0 = up0;
        pp0   = p0;
        p0    = n0;
        p1    = n1;

        __syncthreads();
    }

    // Thread 1023, row i1 = 2047, last valid cell at d = 4094 -> p1 after rotation.
    if (t == 1023) out[0] = sqrtf(p1);
}

extern "C" void kernel_launch(void* const* d_in, const int* in_sizes, int n_in,
                              void* d_out, int out_size)
{
    const float* x = (const float*)d_in[0];
    const float* y = (const float*)d_in[1];
    float* out = (float*)d_out;
    dtw_wavefront_kernel<<<1, 1024>>>(x, y, out);
}

// round 2
// speedup vs baseline: 2.3990x; 2.3990x over previous
#include <cuda_runtime.h>
#include <cuda_bf16.h>

// DTW 2048x2048, anti-diagonal wavefront, single CTA of 256 threads / 8 warps.
// Warp w owns rows [256w, 256w+256); lane l owns 8 consecutive rows starting
// at i0 = 256w + 8l. No __syncthreads in the main loop: warps are pipelined
// with a temporal skew. Warp w publishes its bottom-row (i = 256w+255) value
// for every diagonal into a 64-entry smem ring; warp w+1 consumes it. Pacing
// is done once per 16-diagonal batch via acquire/release progress counters.
//
// Per step (diagonal d), thread computes 8 cells:
//   row r: n[r] = (x[r] - y[d-i0-r])^2 + min(up, left, diag)
//     up   = n[r-1] at d-1 (own reg; r=0: neighbor via shfl_up / ring)
//     left = n[r]   at d-1 (own reg)
//     diag = n[r-1] at d-2 (own reg; r=0: previous step's 'up', carried)
// Out-of-range cells stay +inf (left edge) or finite garbage that only flows
// rightward (right edge) -- never into valid cells. y is staged zero-padded
// in smem; a time-indexed 8-register queue gives 1 LDS of y per thread/step.

#define NLEN  2048
#define NDIAG 4095          // 2*NLEN - 1
#define NW    8             // warps
#define RPT   8             // rows per thread
#define KB    16            // diagonals per batch
#define NB    255           // full batches (255*16 = 4080)
#define TAIL  15            // 4080 + 15 = 4095
#define SRING 64
#define FINF  __int_as_float(0x7f800000)

__device__ __forceinline__ int ld_acq(const int* p) {
    int v; unsigned a = (unsigned)__cvta_generic_to_shared(p);
    asm volatile("ld.acquire.cta.shared::cta.b32 %0, [%1];" : "=r"(v) : "r"(a) : "memory");
    return v;
}
__device__ __forceinline__ void st_rel(int* p, int v) {
    unsigned a = (unsigned)__cvta_generic_to_shared(p);
    asm volatile("st.release.cta.shared::cta.b32 [%0], %1;" :: "r"(a), "r"(v) : "memory");
}

__global__ __launch_bounds__(256, 1)
void dtw_skew_kernel(const float* __restrict__ x,
                     const float* __restrict__ y,
                     float* __restrict__ out)
{
    __shared__ float ysp[3 * NLEN];        // ysp[NLEN + j] = y[j], pads = 0
    __shared__ float ring[NW + 1][SRING];  // ring[w+1][d&63] = warp w bottom row at d
    __shared__ int   prog[NW + 2];         // prog[w+1] = last diag completed by warp w

    const int t    = threadIdx.x;
    const int lane = t & 31;
    const int w    = t >> 5;

    for (int k = t; k < 3 * NLEN; k += 256) {
        int j = k - NLEN;
        ysp[k] = ((unsigned)j < (unsigned)NLEN) ? y[j] : 0.0f;
    }
    for (int k = t; k < (NW + 1) * SRING; k += 256)
        (&ring[0][0])[k] = FINF;           // ring[0] = phantom producer (always +inf)
    if (t < NW + 2)
        prog[t] = (t == 0 || t == NW + 1) ? 0x7fffffff : -1;  // sentinels at both ends

    const int i0 = w * 256 + lane * RPT;   // this thread's top row

    float xv[RPT];
    {
        float4 a = reinterpret_cast<const float4*>(x + i0)[0];
        float4 b = reinterpret_cast<const float4*>(x + i0)[1];
        xv[0]=a.x; xv[1]=a.y; xv[2]=a.z; xv[3]=a.w;
        xv[4]=b.x; xv[5]=b.y; xv[6]=b.z; xv[7]=b.w;
    }

    float p[RPT], pp[RPT], yq[8];
    #pragma unroll
    for (int r = 0; r < RPT; ++r) { p[r] = FINF; pp[r] = FINF; }
    float dTop = (t == 0) ? 0.0f : FINF;   // virtual DTW[-1][-1] = 0 seeds (0,0)

    __syncthreads();

    const float* yb = ysp + NLEN - i0;     // yb[d] = y[d - i0] (zero padded)
    yq[0] = 0.0f;
    #pragma unroll
    for (int k = 1; k <= 7; ++k) yq[(8 - k) & 7] = yb[-k];  // steps -1..-7

    float* ringprev = ring[w];
    float* ringself = ring[w + 1];

    for (int m = 0; m <= NB; ++m) {
        const int d0    = m * KB;
        const int steps = (m == NB) ? TAIL : KB;  // uniform across warps
        const int need1 = d0 + steps - 2;             // producer done through here
        const int need2 = d0 + steps - 1 - (SRING-1); // consumer read ring this far
        int v1, v2;
        do { v1 = ld_acq(prog + w); v2 = ld_acq(prog + w + 2); }
        while (v1 < need1 || v2 < need2);

        const float* ybb = yb + d0;
        float*       rs  = ringself + (d0 & (SRING - 1));  // no wrap within batch
        const float* rpb = ringprev + (d0 & (SRING - 1));
        const float  up_first = ringprev[(d0 - 1) & (SRING - 1)];  // wraps only at u=0

        #pragma unroll
        for (int u = 0; u < KB; ++u) {
            if (u >= steps) break;                      // only trims the tail batch
            const float yn = ybb[u];
            yq[u & 7] = yn;
            float up = __shfl_up_sync(0xffffffffu, p[RPT - 1], 1);
            if (lane == 0) up = (u == 0) ? up_first : rpb[u - 1];

            float nv[RPT];
            {
                const float dy = xv[0] - yn;
                nv[0] = fmaf(dy, dy, fminf(fminf(up, dTop), p[0]));
            }
            #pragma unroll
            for (int r = 1; r < RPT; ++r) {
                const float dy = xv[r] - yq[(u - r) & 7];
                nv[r] = fmaf(dy, dy, fminf(fminf(p[r-1], pp[r-1]), p[r]));
            }
            if (lane == 31) rs[u] = nv[RPT - 1];

            dTop = up;
            #pragma unroll
            for (int r = 0; r < RPT; ++r) { pp[r] = p[r]; p[r] = nv[r]; }
        }

        if (lane == 31) st_rel(prog + w + 1, d0 + steps - 1);
    }

    // Warp 7, lane 31, bottom row 2047: value at d = 4094 is p[7] after rotation.
    if (t == 255) out[0] = sqrtf(p[RPT - 1]);
}

extern "C" void kernel_launch(void* const* d_in, const int* in_sizes, int n_in,
                              void* d_out, int out_size)
{
    const float* x = (const float*)d_in[0];
    const float* y = (const float*)d_in[1];
    float* out = (float*)d_out;
    dtw_skew_kernel<<<1, 256>>>(x, y, out);
}